// round 5
// baseline (speedup 1.0000x reference)
#include <cuda_runtime.h>

// Problem shape (fixed by reference setup_inputs: B=32, S=4096, D=256, fp32)
#define BB   32
#define SS   4096
#define DD   256
#define SD4  (SS * DD / 4)   // float4 per batch row = 262144
#define KCH  64              // blocks per row in kernel A
#define CCH  128             // blocks per row in kernel C

__device__ float2 g_partials[BB * KCH];

// ---------------------------------------------------------------------------
// Kernel A: per-(row, chunk) partial sum/sumsq over the VALID region with
// 8-deep load batching (32KB in flight per block), then zero-fill of this
// block's share of the PADDING region via write-through stores.
// Per-row total work (valid reads + pad writes) == SD4 -> perfectly balanced.
// ---------------------------------------------------------------------------
__global__ void __launch_bounds__(256)
setnorm_partials(const float4* __restrict__ x, const int* __restrict__ lens,
                 float4* __restrict__ out) {
    const int b = blockIdx.x >> 6;          // / KCH
    const int k = blockIdx.x & (KCH - 1);
    const int n4 = __ldg(&lens[b]) * (DD / 4);

    const float4* row  = x   + (size_t)b * SD4;
    float4*       orow = out + (size_t)b * SD4;
    const int tid = threadIdx.x;

    const int chunk = (n4 + KCH - 1) >> 6;
    const int start = k * chunk;
    const int end   = min(start + chunk, n4);

    float s0 = 0.f, s1 = 0.f, s2 = 0.f, s3 = 0.f;
    float q0 = 0.f, q1 = 0.f, q2 = 0.f, q3 = 0.f;

    int j = start + tid;
    // 8 independent loads issued before any consumption -> high MLP
    for (; j + 7 * 256 < end; j += 8 * 256) {
        float4 v0 = row[j + 0 * 256];
        float4 v1 = row[j + 1 * 256];
        float4 v2 = row[j + 2 * 256];
        float4 v3 = row[j + 3 * 256];
        float4 v4 = row[j + 4 * 256];
        float4 v5 = row[j + 5 * 256];
        float4 v6 = row[j + 6 * 256];
        float4 v7 = row[j + 7 * 256];
        s0 += (v0.x + v0.y) + (v0.z + v0.w);
        q0 += (v0.x*v0.x + v0.y*v0.y) + (v0.z*v0.z + v0.w*v0.w);
        s1 += (v1.x + v1.y) + (v1.z + v1.w);
        q1 += (v1.x*v1.x + v1.y*v1.y) + (v1.z*v1.z + v1.w*v1.w);
        s2 += (v2.x + v2.y) + (v2.z + v2.w);
        q2 += (v2.x*v2.x + v2.y*v2.y) + (v2.z*v2.z + v2.w*v2.w);
        s3 += (v3.x + v3.y) + (v3.z + v3.w);
        q3 += (v3.x*v3.x + v3.y*v3.y) + (v3.z*v3.z + v3.w*v3.w);
        s0 += (v4.x + v4.y) + (v4.z + v4.w);
        q0 += (v4.x*v4.x + v4.y*v4.y) + (v4.z*v4.z + v4.w*v4.w);
        s1 += (v5.x + v5.y) + (v5.z + v5.w);
        q1 += (v5.x*v5.x + v5.y*v5.y) + (v5.z*v5.z + v5.w*v5.w);
        s2 += (v6.x + v6.y) + (v6.z + v6.w);
        q2 += (v6.x*v6.x + v6.y*v6.y) + (v6.z*v6.z + v6.w*v6.w);
        s3 += (v7.x + v7.y) + (v7.z + v7.w);
        q3 += (v7.x*v7.x + v7.y*v7.y) + (v7.z*v7.z + v7.w*v7.w);
    }
    for (; j < end; j += 256) {
        float4 a = row[j];
        s0 += (a.x + a.y) + (a.z + a.w);
        q0 += (a.x*a.x + a.y*a.y) + (a.z*a.z + a.w*a.w);
    }
    float s = (s0 + s1) + (s2 + s3);
    float q = (q0 + q1) + (q2 + q3);

    // padding zero-fill: write-through so the out stream does not evict x
    {
        const int pad    = SD4 - n4;
        const int pchunk = (pad + KCH - 1) >> 6;
        const int pstart = n4 + k * pchunk;
        const int pend   = min(pstart + pchunk, SD4);
        const float4 z = make_float4(0.f, 0.f, 0.f, 0.f);
        for (int p = pstart + tid; p < pend; p += 256)
            __stwt(&orow[p], z);
    }

    #pragma unroll
    for (int o = 16; o > 0; o >>= 1) {
        s += __shfl_down_sync(0xffffffffu, s, o);
        q += __shfl_down_sync(0xffffffffu, q, o);
    }
    __shared__ float2 sm[8];
    const int wid = tid >> 5, lid = tid & 31;
    if (lid == 0) sm[wid] = make_float2(s, q);
    __syncthreads();
    if (tid == 0) {
        float2 acc = sm[0];
        #pragma unroll
        for (int w = 1; w < 8; w++) { acc.x += sm[w].x; acc.y += sm[w].y; }
        g_partials[blockIdx.x] = acc;
    }
}

// ---------------------------------------------------------------------------
// Kernel C: each block reduces the 64 partials of its row (cheap, redundant),
// then normalizes its chunk of the VALID region with 4-deep load batching and
// write-through stores. grid = (CCH, BB).
// ---------------------------------------------------------------------------
__global__ void __launch_bounds__(256)
setnorm_apply(const float4* __restrict__ x, const int* __restrict__ lens,
              float4* __restrict__ out) {
    const int b  = blockIdx.y;
    const int k  = blockIdx.x;
    const int n4 = __ldg(&lens[b]) * (DD / 4);
    const int tid = threadIdx.x;

    __shared__ float2 stat;
    if (tid < 32) {
        float s = 0.f, q = 0.f;
        for (int i = tid; i < KCH; i += 32) {
            float2 p = g_partials[b * KCH + i];
            s += p.x; q += p.y;
        }
        #pragma unroll
        for (int o = 16; o > 0; o >>= 1) {
            s += __shfl_down_sync(0xffffffffu, s, o);
            q += __shfl_down_sync(0xffffffffu, q, o);
        }
        if (tid == 0) {
            float cnt  = fmaxf((float)n4 * 4.0f, 1.0f);
            float mean = s / cnt;
            float var  = fmaxf(q / cnt - mean * mean, 0.0f);
            stat = make_float2(mean, rsqrtf(var + 1e-5f));
        }
    }
    __syncthreads();
    const float mean = stat.x, inv = stat.y;

    const int chunk = (n4 + CCH - 1) / CCH;
    const int start = k * chunk;
    const int end   = min(start + chunk, n4);

    const float4* xr   = x   + (size_t)b * SD4;
    float4*       orow = out + (size_t)b * SD4;

    int i = start + tid;
    for (; i + 3 * 256 < end; i += 4 * 256) {
        float4 v0 = xr[i + 0 * 256];
        float4 v1 = xr[i + 1 * 256];
        float4 v2 = xr[i + 2 * 256];
        float4 v3 = xr[i + 3 * 256];
        float4 o0, o1, o2, o3;
        o0.x = (v0.x - mean) * inv; o0.y = (v0.y - mean) * inv;
        o0.z = (v0.z - mean) * inv; o0.w = (v0.w - mean) * inv;
        o1.x = (v1.x - mean) * inv; o1.y = (v1.y - mean) * inv;
        o1.z = (v1.z - mean) * inv; o1.w = (v1.w - mean) * inv;
        o2.x = (v2.x - mean) * inv; o2.y = (v2.y - mean) * inv;
        o2.z = (v2.z - mean) * inv; o2.w = (v2.w - mean) * inv;
        o3.x = (v3.x - mean) * inv; o3.y = (v3.y - mean) * inv;
        o3.z = (v3.z - mean) * inv; o3.w = (v3.w - mean) * inv;
        __stwt(&orow[i + 0 * 256], o0);
        __stwt(&orow[i + 1 * 256], o1);
        __stwt(&orow[i + 2 * 256], o2);
        __stwt(&orow[i + 3 * 256], o3);
    }
    for (; i < end; i += 256) {
        float4 v = xr[i];
        float4 o;
        o.x = (v.x - mean) * inv;
        o.y = (v.y - mean) * inv;
        o.z = (v.z - mean) * inv;
        o.w = (v.w - mean) * inv;
        __stwt(&orow[i], o);
    }
}

extern "C" void kernel_launch(void* const* d_in, const int* in_sizes, int n_in,
                              void* d_out, int out_size) {
    const float4* x   = (const float4*)d_in[0];
    const int*   lens = (const int*)d_in[1];
    float4*      out  = (float4*)d_out;

    setnorm_partials<<<BB * KCH, 256>>>(x, lens, out);
    dim3 gridC(CCH, BB);
    setnorm_apply<<<gridC, 256>>>(x, lens, out);
}

// round 6
// speedup vs baseline: 1.0044x; 1.0044x over previous
#include <cuda_runtime.h>

// Problem shape (fixed by reference setup_inputs: B=32, S=4096, D=256, fp32)
#define BB   32
#define SS   4096
#define DD   256
#define SD4  (SS * DD / 4)   // float4 per batch row = 262144
#define KCH  64              // blocks per row in kernel A
#define CCH  128             // blocks per row in kernel C

__device__ float2 g_partials[BB * KCH];

// ---------------------------------------------------------------------------
// Kernel A: per-(row, chunk) partial sum/sumsq over the VALID region with
// 8-deep load batching (32KB in flight per block), then zero-fill of this
// block's share of the PADDING region via write-through stores.
// Per-row total work (valid reads + pad writes) == SD4 -> perfectly balanced.
// ---------------------------------------------------------------------------
__global__ void __launch_bounds__(256)
setnorm_partials(const float4* __restrict__ x, const int* __restrict__ lens,
                 float4* __restrict__ out) {
    const int b = blockIdx.x >> 6;          // / KCH
    const int k = blockIdx.x & (KCH - 1);
    const int n4 = __ldg(&lens[b]) * (DD / 4);

    const float4* row  = x   + (size_t)b * SD4;
    float4*       orow = out + (size_t)b * SD4;
    const int tid = threadIdx.x;

    const int chunk = (n4 + KCH - 1) >> 6;
    const int start = k * chunk;
    const int end   = min(start + chunk, n4);

    float s0 = 0.f, s1 = 0.f, s2 = 0.f, s3 = 0.f;
    float q0 = 0.f, q1 = 0.f, q2 = 0.f, q3 = 0.f;

    int j = start + tid;
    // 8 independent loads issued before any consumption -> high MLP
    for (; j + 7 * 256 < end; j += 8 * 256) {
        float4 v0 = row[j + 0 * 256];
        float4 v1 = row[j + 1 * 256];
        float4 v2 = row[j + 2 * 256];
        float4 v3 = row[j + 3 * 256];
        float4 v4 = row[j + 4 * 256];
        float4 v5 = row[j + 5 * 256];
        float4 v6 = row[j + 6 * 256];
        float4 v7 = row[j + 7 * 256];
        s0 += (v0.x + v0.y) + (v0.z + v0.w);
        q0 += (v0.x*v0.x + v0.y*v0.y) + (v0.z*v0.z + v0.w*v0.w);
        s1 += (v1.x + v1.y) + (v1.z + v1.w);
        q1 += (v1.x*v1.x + v1.y*v1.y) + (v1.z*v1.z + v1.w*v1.w);
        s2 += (v2.x + v2.y) + (v2.z + v2.w);
        q2 += (v2.x*v2.x + v2.y*v2.y) + (v2.z*v2.z + v2.w*v2.w);
        s3 += (v3.x + v3.y) + (v3.z + v3.w);
        q3 += (v3.x*v3.x + v3.y*v3.y) + (v3.z*v3.z + v3.w*v3.w);
        s0 += (v4.x + v4.y) + (v4.z + v4.w);
        q0 += (v4.x*v4.x + v4.y*v4.y) + (v4.z*v4.z + v4.w*v4.w);
        s1 += (v5.x + v5.y) + (v5.z + v5.w);
        q1 += (v5.x*v5.x + v5.y*v5.y) + (v5.z*v5.z + v5.w*v5.w);
        s2 += (v6.x + v6.y) + (v6.z + v6.w);
        q2 += (v6.x*v6.x + v6.y*v6.y) + (v6.z*v6.z + v6.w*v6.w);
        s3 += (v7.x + v7.y) + (v7.z + v7.w);
        q3 += (v7.x*v7.x + v7.y*v7.y) + (v7.z*v7.z + v7.w*v7.w);
    }
    for (; j < end; j += 256) {
        float4 a = row[j];
        s0 += (a.x + a.y) + (a.z + a.w);
        q0 += (a.x*a.x + a.y*a.y) + (a.z*a.z + a.w*a.w);
    }
    float s = (s0 + s1) + (s2 + s3);
    float q = (q0 + q1) + (q2 + q3);

    // padding zero-fill: write-through so the out stream does not evict x
    {
        const int pad    = SD4 - n4;
        const int pchunk = (pad + KCH - 1) >> 6;
        const int pstart = n4 + k * pchunk;
        const int pend   = min(pstart + pchunk, SD4);
        const float4 z = make_float4(0.f, 0.f, 0.f, 0.f);
        for (int p = pstart + tid; p < pend; p += 256)
            __stwt(&orow[p], z);
    }

    #pragma unroll
    for (int o = 16; o > 0; o >>= 1) {
        s += __shfl_down_sync(0xffffffffu, s, o);
        q += __shfl_down_sync(0xffffffffu, q, o);
    }
    __shared__ float2 sm[8];
    const int wid = tid >> 5, lid = tid & 31;
    if (lid == 0) sm[wid] = make_float2(s, q);
    __syncthreads();
    if (tid == 0) {
        float2 acc = sm[0];
        #pragma unroll
        for (int w = 1; w < 8; w++) { acc.x += sm[w].x; acc.y += sm[w].y; }
        g_partials[blockIdx.x] = acc;
    }
}

// ---------------------------------------------------------------------------
// Kernel C: each block reduces the 64 partials of its row (cheap, redundant),
// then normalizes its chunk of the VALID region with 4-deep load batching and
// write-through stores. grid = (CCH, BB).
// ---------------------------------------------------------------------------
__global__ void __launch_bounds__(256)
setnorm_apply(const float4* __restrict__ x, const int* __restrict__ lens,
              float4* __restrict__ out) {
    const int b  = blockIdx.y;
    const int k  = blockIdx.x;
    const int n4 = __ldg(&lens[b]) * (DD / 4);
    const int tid = threadIdx.x;

    __shared__ float2 stat;
    if (tid < 32) {
        float s = 0.f, q = 0.f;
        for (int i = tid; i < KCH; i += 32) {
            float2 p = g_partials[b * KCH + i];
            s += p.x; q += p.y;
        }
        #pragma unroll
        for (int o = 16; o > 0; o >>= 1) {
            s += __shfl_down_sync(0xffffffffu, s, o);
            q += __shfl_down_sync(0xffffffffu, q, o);
        }
        if (tid == 0) {
            float cnt  = fmaxf((float)n4 * 4.0f, 1.0f);
            float mean = s / cnt;
            float var  = fmaxf(q / cnt - mean * mean, 0.0f);
            stat = make_float2(mean, rsqrtf(var + 1e-5f));
        }
    }
    __syncthreads();
    const float mean = stat.x, inv = stat.y;

    const int chunk = (n4 + CCH - 1) / CCH;
    const int start = k * chunk;
    const int end   = min(start + chunk, n4);

    const float4* xr   = x   + (size_t)b * SD4;
    float4*       orow = out + (size_t)b * SD4;

    int i = start + tid;
    for (; i + 3 * 256 < end; i += 4 * 256) {
        float4 v0 = xr[i + 0 * 256];
        float4 v1 = xr[i + 1 * 256];
        float4 v2 = xr[i + 2 * 256];
        float4 v3 = xr[i + 3 * 256];
        float4 o0, o1, o2, o3;
        o0.x = (v0.x - mean) * inv; o0.y = (v0.y - mean) * inv;
        o0.z = (v0.z - mean) * inv; o0.w = (v0.w - mean) * inv;
        o1.x = (v1.x - mean) * inv; o1.y = (v1.y - mean) * inv;
        o1.z = (v1.z - mean) * inv; o1.w = (v1.w - mean) * inv;
        o2.x = (v2.x - mean) * inv; o2.y = (v2.y - mean) * inv;
        o2.z = (v2.z - mean) * inv; o2.w = (v2.w - mean) * inv;
        o3.x = (v3.x - mean) * inv; o3.y = (v3.y - mean) * inv;
        o3.z = (v3.z - mean) * inv; o3.w = (v3.w - mean) * inv;
        __stwt(&orow[i + 0 * 256], o0);
        __stwt(&orow[i + 1 * 256], o1);
        __stwt(&orow[i + 2 * 256], o2);
        __stwt(&orow[i + 3 * 256], o3);
    }
    for (; i < end; i += 256) {
        float4 v = xr[i];
        float4 o;
        o.x = (v.x - mean) * inv;
        o.y = (v.y - mean) * inv;
        o.z = (v.z - mean) * inv;
        o.w = (v.w - mean) * inv;
        __stwt(&orow[i], o);
    }
}

extern "C" void kernel_launch(void* const* d_in, const int* in_sizes, int n_in,
                              void* d_out, int out_size) {
    const float4* x   = (const float4*)d_in[0];
    const int*   lens = (const int*)d_in[1];
    float4*      out  = (float4*)d_out;

    setnorm_partials<<<BB * KCH, 256>>>(x, lens, out);
    dim3 gridC(CCH, BB);
    setnorm_apply<<<gridC, 256>>>(x, lens, out);
}